// round 8
// baseline (speedup 1.0000x reference)
#include <cuda_runtime.h>
#include <stdint.h>
#include <math.h>

#define Bn 64
#define Ln 4096
#define Dn 128
#define KMAXn 50
#define Pn 24
#define Hn 64
#define MCHUNKS 32

// conv strip config
#define CTHREADS 512
#define STEP_L 64              /* output rows per step */
#define BUFROWS 256            /* circular x buffer rows (power of 2) */
#define STRIP_L 512            /* rows per CTA strip */
#define STEPS (STRIP_L/STEP_L) /* 8 */
#define STRIPS (Ln/STRIP_L)    /* 8 */
#define Rn 8                   /* outputs per thread */
#define JCn 8                  /* tap chunk */
#define XRN (Rn + JCn - 1)     /* 15: sliding x window */

#define SLOT(v) (((v) + 2*BUFROWS) & (BUFROWS-1))

__device__ float g_part[Bn*MCHUNKS*Dn];
__device__ int   g_k[Bn];
__device__ float g_w[Bn*KMAXn*Dn];   // [b][j][d]

// ---------------------------------------------------------------------------
// K1: partial sums over L for the global mean.  grid (32, B), 256 threads.
// ---------------------------------------------------------------------------
__global__ void mean_partial_kernel(const float* __restrict__ x) {
    int c = blockIdx.x, b = blockIdx.y;
    int tid = threadIdx.x;
    int d4 = tid & 31;
    int rs = tid >> 5;
    const float4* x4 = (const float4*)x;
    float4 s = make_float4(0.f, 0.f, 0.f, 0.f);
    long base = ((long)b*Ln + (long)c*128 + rs) * 32 + d4;
    #pragma unroll
    for (int i = 0; i < 16; i++) {
        float4 v = x4[base + (long)i*8*32];
        s.x += v.x; s.y += v.y; s.z += v.z; s.w += v.w;
    }
    __shared__ float4 red[256];
    red[tid] = s;
    __syncthreads();
    if (rs == 0) {
        float4 a = red[d4];
        #pragma unroll
        for (int r = 1; r < 8; r++) {
            float4 v = red[r*32 + d4];
            a.x += v.x; a.y += v.y; a.z += v.z; a.w += v.w;
        }
        float* gp = &g_part[(b*MCHUNKS + c)*Dn + d4*4];
        gp[0] = a.x; gp[1] = a.y; gp[2] = a.z; gp[3] = a.w;
    }
}

// ---------------------------------------------------------------------------
// K2: finish mean, MLP gate -> k[b], masked softmax of trend weights.
// ---------------------------------------------------------------------------
__global__ void gate_softmax_kernel(const float* __restrict__ tw,
                                    const float* __restrict__ w1,
                                    const float* __restrict__ b1,
                                    const float* __restrict__ w2,
                                    const float* __restrict__ b2) {
    int b = blockIdx.x, tid = threadIdx.x;
    __shared__ float mean_s[Dn];
    __shared__ float h_s[Hn];
    __shared__ int k_sh;

    if (tid < Dn) {
        float s = 0.f;
        #pragma unroll
        for (int c = 0; c < MCHUNKS; c++) s += g_part[(b*MCHUNKS + c)*Dn + tid];
        mean_s[tid] = s * (1.0f/(float)Ln);
    }
    __syncthreads();

    if (tid < Hn) {
        float hv = b1[tid];
        #pragma unroll 4
        for (int d = 0; d < Dn; d++) hv = fmaf(mean_s[d], w1[d*Hn + tid], hv);
        h_s[tid] = fmaxf(hv, 0.0f);
    }
    __syncthreads();

    if (tid == 0) {
        float z = b2[0];
        #pragma unroll 4
        for (int j = 0; j < Hn; j++) z = fmaf(h_s[j], w2[j], z);
        float logit = 1.0f/(1.0f + expf(-z));
        float kf = logit * (float)(KMAXn - 5) + 5.0f;
        int k = (int)rintf(kf);              // jnp.round = round-half-even
        if (k < 3) k = 3;
        if (k > KMAXn) k = KMAXn;
        if ((k & 1) == 0) k -= 1;
        if (k < 3) k = 3;
        g_k[b] = k;
        k_sh = k;
    }
    __syncthreads();

    int k = k_sh;
    if (tid < Dn) {
        const float* lg = tw + tid*KMAXn;
        float mx = -1e30f;
        for (int j = 0; j < k; j++) mx = fmaxf(mx, lg[j]);
        float sum = 0.f;
        for (int j = 0; j < k; j++) sum += expf(lg[j] - mx);
        float inv = 1.0f/sum;
        for (int j = 0; j < k; j++)
            g_w[(b*KMAXn + j)*Dn + tid] = expf(lg[j] - mx) * inv;
    }
}

// ---------------------------------------------------------------------------
// K3: persistent-strip depthwise conv, 1 CTA/SM, sliding register window.
// grid (8, B), 512 threads = 64 float2 d-lanes x 8 row-groups (R=8 each).
// 256-row circular smem buffer, cp.async prefetch 2 steps ahead.
// ---------------------------------------------------------------------------
__device__ __forceinline__ void load_rows_async(const float* __restrict__ x,
                                                int b, int vi0, uint32_t sm_x,
                                                int tid, int nchunks) {
    for (int q = tid; q < nchunks; q += CTHREADS) {
        int ro = q >> 5, c4 = q & 31;
        int vi = vi0 + ro;
        int ls = min(max(vi, 0), Ln - 1);
        const float4* src = (const float4*)x + ((long)b*Ln + ls)*32 + c4;
        uint32_t dst = sm_x + (uint32_t)((SLOT(vi)*32 + c4)*16);
        asm volatile("cp.async.cg.shared.global [%0], [%1], 16;\n"
                     :: "r"(dst), "l"(src));
    }
}

__global__ void __launch_bounds__(CTHREADS, 1)
conv_kernel(const float* __restrict__ x, float* __restrict__ out) {
    int b    = blockIdx.y;
    int l0   = blockIdx.x * STRIP_L;
    int tid  = threadIdx.x;

    extern __shared__ float smem[];
    float* x_sm = smem;                    // BUFROWS * Dn floats (128 KB)
    float* w_sm = smem + BUFROWS*Dn;       // KMAXn * Dn floats (25.6 KB)
    uint32_t sm_x = (uint32_t)__cvta_generic_to_shared(x_sm);

    int k = g_k[b];
    int p = k >> 1;

    // per-batch weights -> smem (visible after first step's barrier)
    for (int idx = tid; idx < k*Dn; idx += CTHREADS)
        w_sm[idx] = g_w[b*KMAXn*Dn + idx];

    // prologue: group A = step-0 window, 112 rows [l0-24, l0+87]
    load_rows_async(x, b, l0 - Pn, sm_x, tid, 112*32);
    asm volatile("cp.async.commit_group;\n");
    // group B = step-1 new rows, 64 rows [l0+88, l0+151]
    load_rows_async(x, b, l0 + 88, sm_x, tid, 64*32);
    asm volatile("cp.async.commit_group;\n");

    int d2 = tid & 63;
    int g  = tid >> 6;                     // 0..7, rows 8g..8g+7 of the step
    const float2* x2 = (const float2*)x_sm;
    const float2* w2 = (const float2*)w_sm;
    float2* o2 = (float2*)out;
    const long half = (long)Bn*Ln*(Dn/2);

    for (int s = 0; s < STEPS; s++) {
        int Ls = l0 + s*STEP_L;

        if (s < STEPS - 1) { asm volatile("cp.async.wait_group 1;\n"); }
        else               { asm volatile("cp.async.wait_group 0;\n"); }
        __syncthreads();

        // ---- compute step s ----
        int vbase = Ls + g*Rn - p;          // virtual row of tap 0, r=0
        float2 acc[Rn];
        #pragma unroll
        for (int r = 0; r < Rn; r++) acc[r] = make_float2(0.f, 0.f);

        // sliding x window: xr[i] = row (vbase + jc + i)
        float2 xr[XRN];
        #pragma unroll
        for (int i = 0; i < XRN; i++)
            xr[i] = x2[SLOT(vbase + i)*64 + d2];

        int jc = 0;
        for (; jc + JCn <= k; jc += JCn) {
            float2 wr[JCn];
            #pragma unroll
            for (int t = 0; t < JCn; t++)
                wr[t] = w2[(jc + t)*64 + d2];
            #pragma unroll
            for (int t = 0; t < JCn; t++) {
                #pragma unroll
                for (int r = 0; r < Rn; r++) {
                    acc[r].x = fmaf(wr[t].x, xr[r + t].x, acc[r].x);
                    acc[r].y = fmaf(wr[t].y, xr[r + t].y, acc[r].y);
                }
            }
            // shift window by JCn, refill tail (over-fetch lanes provably unused)
            #pragma unroll
            for (int i = 0; i < XRN - JCn; i++) xr[i] = xr[i + JCn];
            #pragma unroll
            for (int i = XRN - JCn; i < XRN; i++)
                xr[i] = x2[SLOT(vbase + jc + JCn + i)*64 + d2];
        }
        // remainder taps (1..7, compile-time indices via guarded unroll)
        {
            int rem = k - jc;
            #pragma unroll
            for (int t = 0; t < JCn - 1; t++) {
                if (t < rem) {
                    float2 w = w2[(jc + t)*64 + d2];
                    #pragma unroll
                    for (int r = 0; r < Rn; r++) {
                        acc[r].x = fmaf(w.x, xr[t + r].x, acc[r].x);
                        acc[r].y = fmaf(w.y, xr[t + r].y, acc[r].y);
                    }
                }
            }
        }

        // fused epilogue: seasonal = x - trend
        #pragma unroll
        for (int r = 0; r < Rn; r++) {
            int l = Ls + g*Rn + r;
            float2 xv = x2[SLOT(l)*64 + d2];
            float2 t  = acc[r];
            float2 sv = make_float2(xv.x - t.x, xv.y - t.y);
            long off = ((long)b*Ln + l)*(Dn/2) + d2;
            o2[off]        = sv;
            o2[half + off] = t;
        }

        __syncthreads();   // protect live slots from next prefetch

        // prefetch rows for step s+2: [Ls+152, Ls+215]
        if (s + 2 < STEPS) {
            load_rows_async(x, b, Ls + 152, sm_x, tid, 64*32);
            asm volatile("cp.async.commit_group;\n");
        }
    }
}

extern "C" void kernel_launch(void* const* d_in, const int* in_sizes, int n_in,
                              void* d_out, int out_size) {
    const float* x  = (const float*)d_in[0];
    const float* tw = (const float*)d_in[1];
    const float* w1 = (const float*)d_in[2];
    const float* b1 = (const float*)d_in[3];
    const float* w2 = (const float*)d_in[4];
    const float* b2 = (const float*)d_in[5];
    float* out = (float*)d_out;

    int smem_bytes = (BUFROWS*Dn + KMAXn*Dn) * (int)sizeof(float);  // 156672
    cudaFuncSetAttribute(conv_kernel,
                         cudaFuncAttributeMaxDynamicSharedMemorySize, smem_bytes);

    mean_partial_kernel<<<dim3(MCHUNKS, Bn), 256>>>(x);
    gate_softmax_kernel<<<Bn, 128>>>(tw, w1, b1, w2, b2);
    conv_kernel<<<dim3(STRIPS, Bn), CTHREADS, smem_bytes>>>(x, out);
}

// round 11
// speedup vs baseline: 1.1024x; 1.1024x over previous
#include <cuda_runtime.h>
#include <stdint.h>
#include <math.h>

#define Bn 64
#define Ln 4096
#define Dn 128
#define KMAXn 50
#define Pn 24
#define Hn 64
#define MCHUNKS 32

// conv strip config (R7 skeleton: 2 CTA/SM, 32 warps/SM)
#define CTHREADS 512
#define STEP_L 32              /* output rows per step */
#define BUFROWS 128            /* circular x buffer rows (power of 2) */
#define STRIP_L 512            /* rows per CTA strip */
#define STEPS (STRIP_L/STEP_L) /* 16 */
#define STRIPS (Ln/STRIP_L)    /* 8 */
#define Rn 4                   /* outputs per thread */
#define JCn 8                  /* tap chunk */
#define XRN (Rn + JCn - 1)     /* 11: sliding x window */

#define SLOT(v) (((v) + 2*BUFROWS) & (BUFROWS-1))

typedef unsigned long long u64;

// packed f32x2 FMA: d.xy += a.xy * b.xy  (sm_10x FFMA2, PTX-only path)
__device__ __forceinline__ void fma2(u64& d, u64 a, u64 b) {
    asm("fma.rn.f32x2 %0, %1, %2, %0;" : "+l"(d) : "l"(a), "l"(b));
}

__device__ float g_part[Bn*MCHUNKS*Dn];
__device__ int   g_k[Bn];
__device__ float g_w[Bn*KMAXn*Dn];   // [b][j][d]

// ---------------------------------------------------------------------------
// K1: partial sums over L for the global mean.  grid (32, B), 256 threads.
// ---------------------------------------------------------------------------
__global__ void mean_partial_kernel(const float* __restrict__ x) {
    int c = blockIdx.x, b = blockIdx.y;
    int tid = threadIdx.x;
    int d4 = tid & 31;
    int rs = tid >> 5;
    const float4* x4 = (const float4*)x;
    float4 s = make_float4(0.f, 0.f, 0.f, 0.f);
    long base = ((long)b*Ln + (long)c*128 + rs) * 32 + d4;
    #pragma unroll
    for (int i = 0; i < 16; i++) {
        float4 v = x4[base + (long)i*8*32];
        s.x += v.x; s.y += v.y; s.z += v.z; s.w += v.w;
    }
    __shared__ float4 red[256];
    red[tid] = s;
    __syncthreads();
    if (rs == 0) {
        float4 a = red[d4];
        #pragma unroll
        for (int r = 1; r < 8; r++) {
            float4 v = red[r*32 + d4];
            a.x += v.x; a.y += v.y; a.z += v.z; a.w += v.w;
        }
        float* gp = &g_part[(b*MCHUNKS + c)*Dn + d4*4];
        gp[0] = a.x; gp[1] = a.y; gp[2] = a.z; gp[3] = a.w;
    }
}

// ---------------------------------------------------------------------------
// K2: finish mean, MLP gate -> k[b], masked softmax of trend weights.
// ---------------------------------------------------------------------------
__global__ void gate_softmax_kernel(const float* __restrict__ tw,
                                    const float* __restrict__ w1,
                                    const float* __restrict__ b1,
                                    const float* __restrict__ w2,
                                    const float* __restrict__ b2) {
    int b = blockIdx.x, tid = threadIdx.x;
    __shared__ float mean_s[Dn];
    __shared__ float h_s[Hn];
    __shared__ int k_sh;

    if (tid < Dn) {
        float s = 0.f;
        #pragma unroll
        for (int c = 0; c < MCHUNKS; c++) s += g_part[(b*MCHUNKS + c)*Dn + tid];
        mean_s[tid] = s * (1.0f/(float)Ln);
    }
    __syncthreads();

    if (tid < Hn) {
        float hv = b1[tid];
        #pragma unroll 4
        for (int d = 0; d < Dn; d++) hv = fmaf(mean_s[d], w1[d*Hn + tid], hv);
        h_s[tid] = fmaxf(hv, 0.0f);
    }
    __syncthreads();

    if (tid == 0) {
        float z = b2[0];
        #pragma unroll 4
        for (int j = 0; j < Hn; j++) z = fmaf(h_s[j], w2[j], z);
        float logit = 1.0f/(1.0f + expf(-z));
        float kf = logit * (float)(KMAXn - 5) + 5.0f;
        int k = (int)rintf(kf);              // jnp.round = round-half-even
        if (k < 3) k = 3;
        if (k > KMAXn) k = KMAXn;
        if ((k & 1) == 0) k -= 1;
        if (k < 3) k = 3;
        g_k[b] = k;
        k_sh = k;
    }
    __syncthreads();

    int k = k_sh;
    if (tid < Dn) {
        const float* lg = tw + tid*KMAXn;
        float mx = -1e30f;
        for (int j = 0; j < k; j++) mx = fmaxf(mx, lg[j]);
        float sum = 0.f;
        for (int j = 0; j < k; j++) sum += expf(lg[j] - mx);
        float inv = 1.0f/sum;
        for (int j = 0; j < k; j++)
            g_w[(b*KMAXn + j)*Dn + tid] = expf(lg[j] - mx) * inv;
    }
}

// ---------------------------------------------------------------------------
// K3: persistent-strip depthwise conv, 2 CTA/SM, FFMA2 + sliding window.
// grid (8, B), 512 threads = 64 float2 d-lanes x 8 row-groups (R=4 each).
// 128-row circular smem buffer, cp.async prefetch 2 steps ahead.
// ---------------------------------------------------------------------------
__device__ __forceinline__ void load_rows_async(const float* __restrict__ x,
                                                int b, int vi0, uint32_t sm_x,
                                                int tid, int nchunks) {
    for (int q = tid; q < nchunks; q += CTHREADS) {
        int ro = q >> 5, c4 = q & 31;
        int vi = vi0 + ro;
        int ls = min(max(vi, 0), Ln - 1);
        const float4* src = (const float4*)x + ((long)b*Ln + ls)*32 + c4;
        uint32_t dst = sm_x + (uint32_t)((SLOT(vi)*32 + c4)*16);
        asm volatile("cp.async.cg.shared.global [%0], [%1], 16;\n"
                     :: "r"(dst), "l"(src));
    }
}

__global__ void __launch_bounds__(CTHREADS, 2)
conv_kernel(const float* __restrict__ x, float* __restrict__ out) {
    int b    = blockIdx.y;
    int l0   = blockIdx.x * STRIP_L;
    int tid  = threadIdx.x;

    extern __shared__ float smem[];
    float* x_sm = smem;                    // BUFROWS * Dn floats (64 KB)
    float* w_sm = smem + BUFROWS*Dn;       // KMAXn * Dn floats (25.6 KB)
    uint32_t sm_x = (uint32_t)__cvta_generic_to_shared(x_sm);

    int k = g_k[b];
    int p = k >> 1;

    // per-batch weights -> smem (visible after first step's barrier)
    for (int idx = tid; idx < k*Dn; idx += CTHREADS)
        w_sm[idx] = g_w[b*KMAXn*Dn + idx];

    // prologue: group A = step-0 window, 80 rows [l0-24, l0+55]
    load_rows_async(x, b, l0 - Pn, sm_x, tid, 80*32);
    asm volatile("cp.async.commit_group;\n");
    // group B = step-1 new rows, 32 rows [l0+56, l0+87]
    load_rows_async(x, b, l0 + 56, sm_x, tid, 32*32);
    asm volatile("cp.async.commit_group;\n");

    int d2 = tid & 63;
    int g  = tid >> 6;                     // 0..7, rows 4g..4g+3 of the step
    const u64* xs = (const u64*)x_sm;
    const u64* ws = (const u64*)w_sm;
    float2* o2 = (float2*)out;
    const long half = (long)Bn*Ln*(Dn/2);

    for (int s = 0; s < STEPS; s++) {
        int Ls = l0 + s*STEP_L;

        if (s < STEPS - 1) { asm volatile("cp.async.wait_group 1;\n"); }
        else               { asm volatile("cp.async.wait_group 0;\n"); }
        __syncthreads();

        // ---- compute step s ----
        int vbase = Ls + g*Rn - p;          // virtual row of tap 0, r=0
        u64 acc[Rn];
        #pragma unroll
        for (int r = 0; r < Rn; r++) acc[r] = 0ull;

        // sliding x window: xr[i] = row (vbase + jc + i)
        u64 xr[XRN];
        #pragma unroll
        for (int i = 0; i < XRN; i++)
            xr[i] = xs[SLOT(vbase + i)*64 + d2];

        int jc = 0;
        for (; jc + JCn <= k; jc += JCn) {
            u64 wr[JCn];
            #pragma unroll
            for (int t = 0; t < JCn; t++)
                wr[t] = ws[(jc + t)*64 + d2];
            #pragma unroll
            for (int t = 0; t < JCn; t++) {
                #pragma unroll
                for (int r = 0; r < Rn; r++)
                    fma2(acc[r], wr[t], xr[r + t]);
            }
            // shift window by JCn, refill tail (over-fetch lanes never consumed)
            #pragma unroll
            for (int i = 0; i < XRN - JCn; i++) xr[i] = xr[i + JCn];
            #pragma unroll
            for (int i = XRN - JCn; i < XRN; i++)
                xr[i] = xs[SLOT(vbase + jc + JCn + i)*64 + d2];
        }
        // remainder taps (1..7), reuse the window: t+r <= 6+3 = 9 <= 10
        {
            int rem = k - jc;
            #pragma unroll
            for (int t = 0; t < JCn - 1; t++) {
                if (t < rem) {
                    u64 w = ws[(jc + t)*64 + d2];
                    #pragma unroll
                    for (int r = 0; r < Rn; r++)
                        fma2(acc[r], w, xr[t + r]);
                }
            }
        }

        // fused epilogue: seasonal = x - trend
        #pragma unroll
        for (int r = 0; r < Rn; r++) {
            int l = Ls + g*Rn + r;
            u64 xv64 = xs[SLOT(l)*64 + d2];
            float2 xv = *(float2*)&xv64;
            float2 t  = *(float2*)&acc[r];
            float2 sv = make_float2(xv.x - t.x, xv.y - t.y);
            long off = ((long)b*Ln + l)*(Dn/2) + d2;
            o2[off]        = sv;
            o2[half + off] = t;
        }

        __syncthreads();   // protect live slots from next prefetch

        // prefetch rows for step s+2: [Ls+88, Ls+119]
        if (s + 2 < STEPS) {
            load_rows_async(x, b, Ls + 88, sm_x, tid, 32*32);
            asm volatile("cp.async.commit_group;\n");
        }
    }
}

extern "C" void kernel_launch(void* const* d_in, const int* in_sizes, int n_in,
                              void* d_out, int out_size) {
    const float* x  = (const float*)d_in[0];
    const float* tw = (const float*)d_in[1];
    const float* w1 = (const float*)d_in[2];
    const float* b1 = (const float*)d_in[3];
    const float* w2 = (const float*)d_in[4];
    const float* b2 = (const float*)d_in[5];
    float* out = (float*)d_out;

    int smem_bytes = (BUFROWS*Dn + KMAXn*Dn) * (int)sizeof(float);  // 91136
    cudaFuncSetAttribute(conv_kernel,
                         cudaFuncAttributeMaxDynamicSharedMemorySize, smem_bytes);

    mean_partial_kernel<<<dim3(MCHUNKS, Bn), 256>>>(x);
    gate_softmax_kernel<<<Bn, 128>>>(tw, w1, b1, w2, b2);
    conv_kernel<<<dim3(STRIPS, Bn), CTHREADS, smem_bytes>>>(x, out);
}

// round 12
// speedup vs baseline: 1.1843x; 1.0743x over previous
#include <cuda_runtime.h>
#include <stdint.h>
#include <math.h>

#define Bn 64
#define Ln 4096
#define Dn 128
#define KMAXn 50
#define Pn 24
#define Hn 64
#define MCHUNKS 32

// conv strip config: 2 CTA/SM, 256 threads each, R=8 register blocking
#define CTHREADS 256
#define STEP_L 32              /* output rows per step */
#define BUFROWS 128            /* circular x buffer rows (power of 2) */
#define STRIP_L 512            /* rows per CTA strip */
#define STEPS (STRIP_L/STEP_L) /* 16 */
#define STRIPS (Ln/STRIP_L)    /* 8 */
#define Rn 8                   /* outputs per thread */
#define JCn 8                  /* tap chunk */
#define XRN (Rn + JCn - 1)     /* 15: sliding x window */

#define SLOT(v) (((v) + 2*BUFROWS) & (BUFROWS-1))

typedef unsigned long long u64;

// packed f32x2 FMA: d.xy += a.xy * b.xy  (sm_10x FFMA2, PTX-only path)
__device__ __forceinline__ void fma2(u64& d, u64 a, u64 b) {
    asm("fma.rn.f32x2 %0, %1, %2, %0;" : "+l"(d) : "l"(a), "l"(b));
}

__device__ float g_part[Bn*MCHUNKS*Dn];
__device__ int   g_k[Bn];
__device__ float g_w[Bn*KMAXn*Dn];   // [b][j][d]

// ---------------------------------------------------------------------------
// K1: partial sums over L for the global mean.  grid (32, B), 256 threads.
// ---------------------------------------------------------------------------
__global__ void mean_partial_kernel(const float* __restrict__ x) {
    int c = blockIdx.x, b = blockIdx.y;
    int tid = threadIdx.x;
    int d4 = tid & 31;
    int rs = tid >> 5;
    const float4* x4 = (const float4*)x;
    float4 s = make_float4(0.f, 0.f, 0.f, 0.f);
    long base = ((long)b*Ln + (long)c*128 + rs) * 32 + d4;
    #pragma unroll
    for (int i = 0; i < 16; i++) {
        float4 v = x4[base + (long)i*8*32];
        s.x += v.x; s.y += v.y; s.z += v.z; s.w += v.w;
    }
    __shared__ float4 red[256];
    red[tid] = s;
    __syncthreads();
    if (rs == 0) {
        float4 a = red[d4];
        #pragma unroll
        for (int r = 1; r < 8; r++) {
            float4 v = red[r*32 + d4];
            a.x += v.x; a.y += v.y; a.z += v.z; a.w += v.w;
        }
        float* gp = &g_part[(b*MCHUNKS + c)*Dn + d4*4];
        gp[0] = a.x; gp[1] = a.y; gp[2] = a.z; gp[3] = a.w;
    }
}

// ---------------------------------------------------------------------------
// K2: finish mean, MLP gate -> k[b], masked softmax of trend weights.
// ---------------------------------------------------------------------------
__global__ void gate_softmax_kernel(const float* __restrict__ tw,
                                    const float* __restrict__ w1,
                                    const float* __restrict__ b1,
                                    const float* __restrict__ w2,
                                    const float* __restrict__ b2) {
    int b = blockIdx.x, tid = threadIdx.x;
    __shared__ float mean_s[Dn];
    __shared__ float h_s[Hn];
    __shared__ int k_sh;

    if (tid < Dn) {
        float s = 0.f;
        #pragma unroll
        for (int c = 0; c < MCHUNKS; c++) s += g_part[(b*MCHUNKS + c)*Dn + tid];
        mean_s[tid] = s * (1.0f/(float)Ln);
    }
    __syncthreads();

    if (tid < Hn) {
        float hv = b1[tid];
        #pragma unroll 4
        for (int d = 0; d < Dn; d++) hv = fmaf(mean_s[d], w1[d*Hn + tid], hv);
        h_s[tid] = fmaxf(hv, 0.0f);
    }
    __syncthreads();

    if (tid == 0) {
        float z = b2[0];
        #pragma unroll 4
        for (int j = 0; j < Hn; j++) z = fmaf(h_s[j], w2[j], z);
        float logit = 1.0f/(1.0f + expf(-z));
        float kf = logit * (float)(KMAXn - 5) + 5.0f;
        int k = (int)rintf(kf);              // jnp.round = round-half-even
        if (k < 3) k = 3;
        if (k > KMAXn) k = KMAXn;
        if ((k & 1) == 0) k -= 1;
        if (k < 3) k = 3;
        g_k[b] = k;
        k_sh = k;
    }
    __syncthreads();

    int k = k_sh;
    if (tid < Dn) {
        const float* lg = tw + tid*KMAXn;
        float mx = -1e30f;
        for (int j = 0; j < k; j++) mx = fmaxf(mx, lg[j]);
        float sum = 0.f;
        for (int j = 0; j < k; j++) sum += expf(lg[j] - mx);
        float inv = 1.0f/sum;
        for (int j = 0; j < k; j++)
            g_w[(b*KMAXn + j)*Dn + tid] = expf(lg[j] - mx) * inv;
    }
}

// ---------------------------------------------------------------------------
// K3: persistent-strip depthwise conv, 2 CTA/SM x 256 thr, R=8 + FFMA2.
// grid (8, B). 64 float2 d-lanes x 4 row-groups (R=8 rows each) = 32 rows/step.
// 128-row circular smem buffer, cp.async prefetch 2 steps ahead.
// ---------------------------------------------------------------------------
__device__ __forceinline__ void load_rows_async(const float* __restrict__ x,
                                                int b, int vi0, uint32_t sm_x,
                                                int tid, int nchunks) {
    for (int q = tid; q < nchunks; q += CTHREADS) {
        int ro = q >> 5, c4 = q & 31;
        int vi = vi0 + ro;
        int ls = min(max(vi, 0), Ln - 1);
        const float4* src = (const float4*)x + ((long)b*Ln + ls)*32 + c4;
        uint32_t dst = sm_x + (uint32_t)((SLOT(vi)*32 + c4)*16);
        asm volatile("cp.async.cg.shared.global [%0], [%1], 16;\n"
                     :: "r"(dst), "l"(src));
    }
}

__global__ void __launch_bounds__(CTHREADS, 2)
conv_kernel(const float* __restrict__ x, float* __restrict__ out) {
    int b    = blockIdx.y;
    int l0   = blockIdx.x * STRIP_L;
    int tid  = threadIdx.x;

    extern __shared__ float smem[];
    float* x_sm = smem;                    // BUFROWS * Dn floats (64 KB)
    float* w_sm = smem + BUFROWS*Dn;       // KMAXn * Dn floats (25.6 KB)
    uint32_t sm_x = (uint32_t)__cvta_generic_to_shared(x_sm);

    int k = g_k[b];
    int p = k >> 1;

    // per-batch weights -> smem (visible after first step's barrier)
    for (int idx = tid; idx < k*Dn; idx += CTHREADS)
        w_sm[idx] = g_w[b*KMAXn*Dn + idx];

    // prologue: group A = step-0 window, 80 rows [l0-24, l0+55]
    load_rows_async(x, b, l0 - Pn, sm_x, tid, 80*32);
    asm volatile("cp.async.commit_group;\n");
    // group B = step-1 new rows, 32 rows [l0+56, l0+87]
    load_rows_async(x, b, l0 + 56, sm_x, tid, 32*32);
    asm volatile("cp.async.commit_group;\n");

    int d2 = tid & 63;
    int g  = tid >> 6;                     // 0..3, rows 8g..8g+7 of the step
    const u64* xs = (const u64*)x_sm;
    const u64* ws = (const u64*)w_sm;
    float2* o2 = (float2*)out;
    const long half = (long)Bn*Ln*(Dn/2);

    for (int s = 0; s < STEPS; s++) {
        int Ls = l0 + s*STEP_L;

        if (s < STEPS - 1) { asm volatile("cp.async.wait_group 1;\n"); }
        else               { asm volatile("cp.async.wait_group 0;\n"); }
        __syncthreads();

        // ---- compute step s ----
        int vbase = Ls + g*Rn - p;          // virtual row of tap 0, r=0
        u64 acc[Rn];
        #pragma unroll
        for (int r = 0; r < Rn; r++) acc[r] = 0ull;

        // sliding x window: xr[i] = row (vbase + jc + i)
        u64 xr[XRN];
        #pragma unroll
        for (int i = 0; i < XRN; i++)
            xr[i] = xs[SLOT(vbase + i)*64 + d2];

        int jc = 0;
        for (; jc + JCn <= k; jc += JCn) {
            u64 wr[JCn];
            #pragma unroll
            for (int t = 0; t < JCn; t++)
                wr[t] = ws[(jc + t)*64 + d2];
            #pragma unroll
            for (int t = 0; t < JCn; t++) {
                #pragma unroll
                for (int r = 0; r < Rn; r++)
                    fma2(acc[r], wr[t], xr[r + t]);
            }
            // shift window by JCn, refill tail (over-fetch lanes never consumed;
            // worst-case reach <= Ls+87 which is loaded, and never aliases the
            // in-flight prefetch rows [Ls+88, Ls+119] in the circular buffer)
            #pragma unroll
            for (int i = 0; i < XRN - JCn; i++) xr[i] = xr[i + JCn];
            #pragma unroll
            for (int i = XRN - JCn; i < XRN; i++)
                xr[i] = xs[SLOT(vbase + jc + JCn + i)*64 + d2];
        }
        // remainder taps (1..7), reuse the window: t+r <= 6+7 = 13 <= 14
        {
            int rem = k - jc;
            #pragma unroll
            for (int t = 0; t < JCn - 1; t++) {
                if (t < rem) {
                    u64 w = ws[(jc + t)*64 + d2];
                    #pragma unroll
                    for (int r = 0; r < Rn; r++)
                        fma2(acc[r], w, xr[t + r]);
                }
            }
        }

        // fused epilogue: seasonal = x - trend
        #pragma unroll
        for (int r = 0; r < Rn; r++) {
            int l = Ls + g*Rn + r;
            u64 xv64 = xs[SLOT(l)*64 + d2];
            float2 xv = *(float2*)&xv64;
            float2 t  = *(float2*)&acc[r];
            float2 sv = make_float2(xv.x - t.x, xv.y - t.y);
            long off = ((long)b*Ln + l)*(Dn/2) + d2;
            o2[off]        = sv;
            o2[half + off] = t;
        }

        __syncthreads();   // protect live slots from next prefetch

        // prefetch rows for step s+2: [Ls+88, Ls+119]
        if (s + 2 < STEPS) {
            load_rows_async(x, b, Ls + 88, sm_x, tid, 32*32);
            asm volatile("cp.async.commit_group;\n");
        }
    }
}

extern "C" void kernel_launch(void* const* d_in, const int* in_sizes, int n_in,
                              void* d_out, int out_size) {
    const float* x  = (const float*)d_in[0];
    const float* tw = (const float*)d_in[1];
    const float* w1 = (const float*)d_in[2];
    const float* b1 = (const float*)d_in[3];
    const float* w2 = (const float*)d_in[4];
    const float* b2 = (const float*)d_in[5];
    float* out = (float*)d_out;

    int smem_bytes = (BUFROWS*Dn + KMAXn*Dn) * (int)sizeof(float);  // 91136
    cudaFuncSetAttribute(conv_kernel,
                         cudaFuncAttributeMaxDynamicSharedMemorySize, smem_bytes);

    mean_partial_kernel<<<dim3(MCHUNKS, Bn), 256>>>(x);
    gate_softmax_kernel<<<Bn, 128>>>(tw, w1, b1, w2, b2);
    conv_kernel<<<dim3(STRIPS, Bn), CTHREADS, smem_bytes>>>(x, out);
}